// round 13
// baseline (speedup 1.0000x reference)
#include <cuda_runtime.h>
#include <math.h>

#define NJ   68
#define RES  32
#define NB   2048
#define DIMX 96
#define NBLK 64
#define NTHR 384
#define CHEB_B 0.85f
#define CHEB_DEG 5
#define CHEB_STAGES 3
// dyn smem (max over phases): phase2 C(96*97)+Y0(384)+Y1(384)+P(1536) floats
#define DSM_BYTES ((96 * 97 + 384 + 384 + 1536) * 4)

// -------------------- device globals (no allocs) --------------------
__device__ float g_S[DIMX * DIMX];      // Gram; zeroed by block 0 at each call's end-of-use
__device__ float g_colP[NBLK * DIMX];   // per-block column-sum partials
__device__ float g_colL[NBLK * DIMX];
__device__ int   g_cnt[NBLK];           // per-block IoU counts
__device__ int   g_bar2;                // spin barrier (reset by block 0)

// runtime knot lookups (exactly match reference construction)
__device__ __forceinline__ float knU(int i) {   // n=68,p=2,L=71
    return (i < 3) ? 0.0f : ((i >= 68) ? 1.0f : (float)((double)(i - 2) / 66.0));
}
__device__ __forceinline__ float knV(int i) {   // n=68,q=3,L=72
    return (i < 4) ? 0.0f : ((i >= 68) ? 1.0f : (float)((double)(i - 3) / 65.0));
}

__global__ void __launch_bounds__(NTHR)
k_fused(const float* __restrict__ pred, const float* __restrict__ label,
        float* __restrict__ out) {
    extern __shared__ float dsm[];
    // phase 0/1 carve
    float* Xsm = dsm;                    // 64 x 96 = 6144 (pred rows 0-31, label 32-63)
    float* sPL = dsm + 6144;             // 4*204 pred | 4*204 label = 1632
    float* cPL = dsm + 6144 + 1632;      // 4*96 | 4*96 = 768
    // phase 2 carve (block 0 only; Xsm/sPL/cPL dead by then)
    float* C  = dsm;                     // 96*97
    float* Y0 = dsm + 96 * 97;
    float* Y1 = Y0 + 384;
    float* P  = Y1 + 384;                // 4*96*4

    __shared__ float sv_s[RES];
    __shared__ float w_s[RES * 3];
    __shared__ int   base_s[RES];
    __shared__ int   cnt_s;
    __shared__ float S4[16], R4[16], Rinv[4], W4[16];
    __shared__ float T4[4 * 5], V4[4 * 5];
    __shared__ float rc2[2], rs2[2];
    __shared__ int   rp2[2], rq2[2];
    __shared__ float dvec[DIMX], mus[DIMX], gvec[4];

    const int b = blockIdx.x;
    const int t = threadIdx.x;
    const int sub = t / 96;      // 0..3
    const int tt  = t - sub * 96;

    // ---------------- Phase 0: sparse basis (warp 0) ----------------
    if (t == 0) cnt_s = 0;
    if (t < 32) {
        const int uj = t;
        const float u = (float)((double)uj / 31.0);
        {   // Nu (p=2): window i = s-2 .. s+1
            int s = -1;
            for (int i = 0; i < 70; i++)
                if (knU(i) <= u && u < knU(i + 1)) s = i;
            float w[4] = {0.0f, 0.0f, 0.0f, 0.0f};
            int base = 0;
            if (s >= 0) {
                base = s - 2;
                w[2] = 1.0f;
#pragma unroll
                for (int d = 1; d <= 2; d++) {
#pragma unroll
                    for (int a = 0; a < 3; a++) {
                        int i = s - 2 + a;
                        float ld = knU(i + d) - knU(i);
                        float rd = knU(i + d + 1) - knU(i + 1);
                        float t1 = (ld == 0.0f) ? 0.0f : (u - knU(i)) / ld * w[a];
                        float t2 = (rd == 0.0f) ? 0.0f : (knU(i + d + 1) - u) / rd * w[a + 1];
                        w[a] = t1 + t2;
                    }
                }
            }
            base_s[uj] = base;
            w_s[uj * 3 + 0] = w[0];
            w_s[uj * 3 + 1] = w[1];
            w_s[uj * 3 + 2] = w[2];
        }
        {   // Nv (q=3): window i = s-3 .. s+1; only the sum sv is needed
            int s = -1;
            for (int i = 0; i < 71; i++)
                if (knV(i) <= u && u < knV(i + 1)) s = i;
            float v[5] = {0.0f, 0.0f, 0.0f, 0.0f, 0.0f};
            if (s >= 0) {
                v[3] = 1.0f;
#pragma unroll
                for (int d = 1; d <= 3; d++) {
#pragma unroll
                    for (int a = 0; a < 4; a++) {
                        int i = s - 3 + a;
                        float ld = knV(i + d) - knV(i);
                        float rd = knV(i + d + 1) - knV(i + 1);
                        float t1 = (ld == 0.0f) ? 0.0f : (u - knV(i)) / ld * v[a];
                        float t2 = (rd == 0.0f) ? 0.0f : (knV(i + d + 1) - u) / rd * v[a + 1];
                        v[a] = t1 + t2;
                    }
                }
            }
            sv_s[uj] = v[0] + v[1] + v[2] + v[3];   // ascending-i order, zeros exact no-ops
        }
    }
    __syncthreads();

    // ---------------- Phase 1a: 32 batches/block, 3-FMA curves ----------------
    float colP_acc = 0.0f, colL_acc = 0.0f;
    const int u = tt / 3, c = tt - u * 3;
    const int base = base_s[u];
    const float w0 = w_s[u * 3], w1 = w_s[u * 3 + 1], w2 = w_s[u * 3 + 2];
    for (int it = 0; it < 8; it++) {
        int batch = b * 32 + it * 4 + sub;
        for (int i = tt; i < 204; i += 96) {
            sPL[sub * 204 + i]       = pred[batch * 204 + i];
            sPL[816 + sub * 204 + i] = label[batch * 204 + i];
        }
        __syncthreads();
        const float* cp = &sPL[sub * 204];
        const float* cl = &sPL[816 + sub * 204];
        float aP = 0.0f, aL = 0.0f;
        aP += cp[(base + 0) * 3 + c] * w0;
        aP += cp[(base + 1) * 3 + c] * w1;
        aP += cp[(base + 2) * 3 + c] * w2;
        aL += cl[(base + 0) * 3 + c] * w0;
        aL += cl[(base + 1) * 3 + c] * w1;
        aL += cl[(base + 2) * 3 + c] * w2;
        Xsm[(it * 4 + sub) * 96 + tt]        = aP;
        Xsm[(32 + it * 4 + sub) * 96 + tt]   = aL;
        cPL[sub * 96 + tt]       = aP;
        cPL[384 + sub * 96 + tt] = aL;
        colP_acc += aP;
        colL_acc += aL;
        __syncthreads();
        if (tt < 32) {   // warp-aligned per sub
            float p0 = cPL[sub * 96 + tt * 3], p1 = cPL[sub * 96 + tt * 3 + 1], p2 = cPL[sub * 96 + tt * 3 + 2];
            float l0 = cPL[384 + sub * 96 + tt * 3], l1 = cPL[384 + sub * 96 + tt * 3 + 1], l2 = cPL[384 + sub * 96 + tt * 3 + 2];
            int cnt = 0;
#pragma unroll
            for (int v = 0; v < RES; v++) {
                float sv = sv_s[v];
                float d0 = p0 * sv - l0 * sv;
                float d1 = p1 * sv - l1 * sv;
                float d2 = p2 * sv - l2 * sv;
                float s = (d0 * d0 + d1 * d1) + d2 * d2;
                cnt += (s < 0.25f) ? 1 : 0;
            }
#pragma unroll
            for (int o = 16; o > 0; o >>= 1)
                cnt += __shfl_down_sync(0xffffffffu, cnt, o);
            if (tt == 0) atomicAdd(&cnt_s, cnt);
        }
        __syncthreads();
    }
    // colsum partials (4 subs -> 1)
    cPL[sub * 96 + tt]       = colP_acc;
    cPL[384 + sub * 96 + tt] = colL_acc;
    __syncthreads();
    if (sub == 0) {
        g_colP[b * 96 + tt] = cPL[tt] + cPL[96 + tt] + cPL[192 + tt] + cPL[288 + tt];
        g_colL[b * 96 + tt] = cPL[384 + tt] + cPL[480 + tt] + cPL[576 + tt] + cPL[672 + tt];
    }
    if (t == 0) g_cnt[b] = cnt_s;
    __syncthreads();

    // ---------------- Phase 1b: Gram of this block's own 64 rows (smem) -------
    {
        const int ti = t / 24, tj = t - (t / 24) * 24;   // 16 x 24
        const int i0 = ti * 6, j0 = tj * 4;
        float acc[24];
#pragma unroll
        for (int k = 0; k < 24; k++) acc[k] = 0.0f;
#pragma unroll 4
        for (int row = 0; row < 64; row++) {
            const float* xr = &Xsm[row * 96];
            float2 A0 = *(const float2*)(xr + i0);
            float2 A1 = *(const float2*)(xr + i0 + 2);
            float2 A2 = *(const float2*)(xr + i0 + 4);
            float4 Bv = *(const float4*)(xr + j0);
            float xi[6] = {A0.x, A0.y, A1.x, A1.y, A2.x, A2.y};
            float xj[4] = {Bv.x, Bv.y, Bv.z, Bv.w};
#pragma unroll
            for (int a = 0; a < 6; a++)
#pragma unroll
                for (int bb = 0; bb < 4; bb++)
                    acc[a * 4 + bb] += xi[a] * xj[bb];
        }
#pragma unroll
        for (int a = 0; a < 6; a++)
#pragma unroll
            for (int bb = 0; bb < 4; bb++)
                atomicAdd(&g_S[(i0 + a) * 96 + (j0 + bb)], acc[a * 4 + bb]);
    }

    // ---------------- Barrier (arrive; block 0 waits) ----------------
    __syncthreads();
    if (t == 0) { __threadfence(); atomicAdd(&g_bar2, 1); }
    if (b != 0) return;
    if (t == 0) {
        while (atomicAdd(&g_bar2, 0) < NBLK) __nanosleep(100);
        __threadfence();
    }
    __syncthreads();

    // ---------------- Phase 2 (block 0 only): eig + finalize ----------------
    if (t < DIMX) {
        double sp = 0.0, sl = 0.0;
        for (int k = 0; k < NBLK; k++) {
            sp += (double)g_colP[k * 96 + t];
            sl += (double)g_colL[k * 96 + t];
        }
        mus[t]  = (float)((sp + sl) / 4096.0);
        dvec[t] = (float)(sp / 2048.0 - sl / 2048.0);
    }
    __syncthreads();
    for (int idx = t; idx < 96 * 96; idx += NTHR) {
        int i = idx / 96, j = idx - i * 96;
        float val = g_S[idx];
        C[i * 97 + j] = (val - 4096.0f * mus[i] * mus[j]) * (1.0f / 4095.0f);
        g_S[idx] = 0.0f;   // re-zero for next graph replay
    }
    if (t < 96) {
#pragma unroll
        for (int s = 0; s < 4; s++)
            Y0[t * 4 + s] = cosf(0.7f * (float)((t + 1) * (s + 1))) +
                            ((t == s) ? 0.05f : 0.0f);
    }
    __syncthreads();

    float* cur = Y0;
    float* prv = Y1;
    const int r = t % 96;
    const int g = t / 96;

#define MATVEC(SRC)                                                       \
    {                                                                     \
        float a0=0,a1=0,a2=0,a3=0;                                        \
        int j0_ = g * 24;                                                 \
        _Pragma("unroll 4")                                               \
        for (int jj = 0; jj < 24; jj++) {                                 \
            int j = j0_ + jj;                                             \
            float cc_ = C[r * 97 + j];                                    \
            float4 y = *(const float4*)&SRC[j * 4];                       \
            a0 += cc_ * y.x; a1 += cc_ * y.y; a2 += cc_ * y.z; a3 += cc_ * y.w; \
        }                                                                 \
        *(float4*)&P[(g * 96 + r) * 4] = make_float4(a0, a1, a2, a3);     \
    }                                                                     \
    __syncthreads();

#define REDUCE3(ca, cb, cc, CUR, PRV, DST)                                \
    {                                                                     \
        float cy = P[t] + P[384 + t] + P[768 + t] + P[1152 + t];          \
        DST[t] = (ca) * cy + (cb) * CUR[t] + (cc) * PRV[t];               \
    }                                                                     \
    __syncthreads();

#define REDUCE2(ca, cb, CUR, DST)                                         \
    {                                                                     \
        float cy = P[t] + P[384 + t] + P[768 + t] + P[1152 + t];          \
        DST[t] = (ca) * cy + (cb) * CUR[t];                               \
    }                                                                     \
    __syncthreads();

#define GRAM4(SRC)                                                        \
    if (t < 64) {                                                         \
        int pair = t >> 2, sb = t & 3;                                    \
        int a = pair >> 2, bb = pair & 3;                                 \
        float s = 0.0f;                                                   \
        for (int i = sb * 24; i < sb * 24 + 24; i++)                      \
            s += SRC[i * 4 + a] * SRC[i * 4 + bb];                        \
        s += __shfl_down_sync(0xffffffffu, s, 1);                         \
        s += __shfl_down_sync(0xffffffffu, s, 2);                         \
        if (sb == 0) S4[pair] = s;                                        \
    }                                                                     \
    __syncthreads();

#define CHOL4()                                                           \
    if (t == 0) {                                                         \
        float tr = S4[0] + S4[5] + S4[10] + S4[15];                       \
        float ridge = 1e-6f * tr;                                         \
        _Pragma("unroll")                                                 \
        for (int k = 0; k < 4; k++) S4[k * 4 + k] += ridge;               \
        _Pragma("unroll")                                                 \
        for (int k = 0; k < 4; k++) {                                     \
            float dk = sqrtf(fmaxf(S4[k * 4 + k], 1e-30f));               \
            float inv = 1.0f / dk;                                        \
            R4[k * 4 + k] = dk; Rinv[k] = inv;                            \
            for (int j = k + 1; j < 4; j++)                               \
                R4[k * 4 + j] = S4[k * 4 + j] * inv;                      \
            for (int i = k + 1; i < 4; i++)                               \
                for (int j = i; j < 4; j++)                               \
                    S4[i * 4 + j] -= R4[k * 4 + i] * R4[k * 4 + j];       \
        }                                                                 \
    }                                                                     \
    __syncthreads();

#define RSOLVE(SRC, DST)                                                  \
    if (t < 96) {                                                         \
        float z[4], y[4];                                                 \
        _Pragma("unroll")                                                 \
        for (int s = 0; s < 4; s++) z[s] = SRC[t * 4 + s];                \
        _Pragma("unroll")                                                 \
        for (int s = 0; s < 4; s++) {                                     \
            float v = z[s];                                               \
            for (int k = 0; k < s; k++) v -= y[k] * R4[k * 4 + s];        \
            y[s] = v * Rinv[s];                                           \
        }                                                                 \
        _Pragma("unroll")                                                 \
        for (int s = 0; s < 4; s++) DST[t * 4 + s] = y[s];                \
    }                                                                     \
    __syncthreads();

    const float c1 = 2.0f / CHEB_B;
    const float c4 = 4.0f / CHEB_B;

    for (int stage = 0; stage < CHEB_STAGES; stage++) {
        MATVEC(cur);
        REDUCE2(c1, -1.0f, cur, prv);
        { float* tmp = cur; cur = prv; prv = tmp; }
        for (int k = 0; k < CHEB_DEG - 1; k++) {
            MATVEC(cur);
            REDUCE3(c4, -2.0f, -1.0f, cur, prv, prv);
            { float* tmp = cur; cur = prv; prv = tmp; }
        }
        GRAM4(cur);
        CHOL4();
        RSOLVE(cur, cur);
    }

    MATVEC(cur);
    REDUCE2(1.0f, 0.0f, cur, prv);

    if (t < 64) {
        int pair = t >> 2, sb = t & 3;
        int a = pair >> 2, bb = pair & 3;
        float s = 0.0f;
        for (int i = sb * 24; i < sb * 24 + 24; i++)
            s += cur[i * 4 + a] * prv[i * 4 + bb];
        s += __shfl_down_sync(0xffffffffu, s, 1);
        s += __shfl_down_sync(0xffffffffu, s, 2);
        if (sb == 0) W4[pair] = s;
    }
    __syncthreads();
    if (t < 16) {
        int a = t >> 2, bb = t & 3;
        T4[a * 5 + bb] = 0.5f * (W4[a * 4 + bb] + W4[bb * 4 + a]);
    }
    if (t >= 16 && t < 32) {
        int e = t - 16;
        int j = e >> 2, k = e & 3;
        V4[j * 5 + k] = (j == k) ? 1.0f : 0.0f;
    }
    __syncthreads();

    if (t >= 32 && t < 36) {
        int a = t - 32;
        float s = 0.0f;
        for (int i = 0; i < 96; i++) s += cur[i * 4 + a] * dvec[i];
        gvec[a] = s;
    }

    if (t < 32) {
        for (int sweep = 0; sweep < 6; sweep++) {
            for (int rr = 0; rr < 3; rr++) {
                if (t < 2) {
                    int p, q;
                    if (t == 0) { p = 3; q = rr; }
                    else { p = (rr + 1) % 3; q = (rr + 2) % 3; }
                    rp2[t] = p; rq2[t] = q;
                    float app = T4[p * 5 + p];
                    float aqq = T4[q * 5 + q];
                    float apq = T4[p * 5 + q];
                    float cc_ = 1.0f, ss_ = 0.0f;
                    if (fabsf(apq) > 1e-30f) {
                        float tau = (aqq - app) / (2.0f * apq);
                        float tv = (tau >= 0.0f)
                                       ? 1.0f / (tau + sqrtf(1.0f + tau * tau))
                                       : 1.0f / (tau - sqrtf(1.0f + tau * tau));
                        cc_ = rsqrtf(1.0f + tv * tv);
                        ss_ = tv * cc_;
                    }
                    rc2[t] = cc_; rs2[t] = ss_;
                }
                __syncwarp();
                if (t < 4) {
                    int a = t >> 1, bb = t & 1;
                    int pa = rp2[a], qa = rq2[a];
                    int pb = rp2[bb], qb = rq2[bb];
                    float ca = rc2[a], sa = rs2[a];
                    float cb2 = rc2[bb], sb2 = rs2[bb];
                    float x00 = T4[pa * 5 + pb], x01 = T4[pa * 5 + qb];
                    float x10 = T4[qa * 5 + pb], x11 = T4[qa * 5 + qb];
                    float y00 = ca * x00 - sa * x10;
                    float y01 = ca * x01 - sa * x11;
                    float y10 = sa * x00 + ca * x10;
                    float y11 = sa * x01 + ca * x11;
                    T4[pa * 5 + pb] = cb2 * y00 - sb2 * y01;
                    T4[pa * 5 + qb] = sb2 * y00 + cb2 * y01;
                    T4[qa * 5 + pb] = cb2 * y10 - sb2 * y11;
                    T4[qa * 5 + qb] = sb2 * y10 + cb2 * y11;
                }
                if (t >= 8 && t < 16) {
                    int e = t - 8;
                    int j = e >> 1, k = e & 1;
                    int p = rp2[k], q = rq2[k];
                    float cc_ = rc2[k], ss_ = rs2[k];
                    float vp = V4[j * 5 + p], vq = V4[j * 5 + q];
                    V4[j * 5 + p] = cc_ * vp - ss_ * vq;
                    V4[j * 5 + q] = ss_ * vp + cc_ * vq;
                }
                __syncwarp();
            }
        }
    }
    __syncthreads();

    if (t == 0) {
        int imin = 0;
        float vmin = T4[0];
#pragma unroll
        for (int i = 1; i < 4; i++) {
            float e = T4[i * 5 + i];
            if (e < vmin) { vmin = e; imin = i; }
        }
        float ssum = 0.0f;
#pragma unroll
        for (int k = 0; k < 4; k++) {
            if (k == imin) continue;
            float pr = 0.0f;
            for (int a = 0; a < 4; a++) pr += V4[a * 5 + k] * gvec[a];
            ssum += pr * pr;
        }
        float sv2 = 0.0f;
        for (int v = 0; v < RES; v++) sv2 += sv_s[v] * sv_s[v];
        float dist_pca = sqrtf(sv2) * sqrtf(ssum);
        float pca_loss = 1.0f - dist_pca;

        int icnt = 0;
        for (int k = 0; k < NBLK; k++) icnt += g_cnt[k];
        float inter = (float)icnt;
        float uni = 2048.0f - inter;   // reference: P + P - inter
        float iou_loss = 1.0f - inter / uni;

        out[0] = pca_loss + iou_loss;

        atomicExch(&g_bar2, 0);   // reset for next graph replay
    }
}

// -------------------- launcher --------------------
extern "C" void kernel_launch(void* const* d_in, const int* in_sizes, int n_in,
                              void* d_out, int out_size) {
    const float* pred  = (const float*)d_in[0];
    const float* label = (const float*)d_in[1];
    float* out = (float*)d_out;

    cudaFuncSetAttribute(k_fused, cudaFuncAttributeMaxDynamicSharedMemorySize,
                         DSM_BYTES);
    k_fused<<<NBLK, NTHR, DSM_BYTES>>>(pred, label, out);
}

// round 14
// speedup vs baseline: 1.1494x; 1.1494x over previous
#include <cuda_runtime.h>
#include <math.h>

#define NJ   68
#define RES  32
#define NB   2048
#define DIMX 96
#define NBLK 64
#define NTHR 384
#define CHEB_B 0.85f
#define CHEB_DEG 5
#define CHEB_STAGES 2
// dyn smem: max(phase1: 6144+3264+1536, phase2: 96*97+384+384+1536) floats
#define DSM_BYTES ((96 * 97 + 384 + 384 + 1536) * 4)

// -------------------- device globals (no allocs) --------------------
__device__ float g_S[DIMX * DIMX];      // Gram; re-zeroed by block 0 in phase 2
__device__ float g_colP[NBLK * DIMX];
__device__ float g_colL[NBLK * DIMX];
__device__ int   g_cnt[NBLK];
__device__ int   g_bar2;                // spin barrier (reset by block 0)

__device__ __forceinline__ float knU(int i) {   // n=68,p=2,L=71
    return (i < 3) ? 0.0f : ((i >= 68) ? 1.0f : (float)((double)(i - 2) / 66.0));
}
__device__ __forceinline__ float knV(int i) {   // n=68,q=3,L=72
    return (i < 4) ? 0.0f : ((i >= 68) ? 1.0f : (float)((double)(i - 3) / 65.0));
}

__global__ void __launch_bounds__(NTHR)
k_fused(const float* __restrict__ pred, const float* __restrict__ label,
        float* __restrict__ out) {
    extern __shared__ float dsm[];
    // phase 0/1 carve
    float* Xsm = dsm;                    // 64 x 96 (pred rows 0-31, label 32-63)
    float* sPL = dsm + 6144;             // 2 buffers x 1632
    float* cPL = dsm + 6144 + 3264;      // 2 buffers x 768
    // phase 2 carve (block 0 only)
    float* C  = dsm;                     // 96*97
    float* Y0 = dsm + 96 * 97;
    float* Y1 = Y0 + 384;
    float* P  = Y1 + 384;                // 4*96*4

    __shared__ float sv_s[RES];
    __shared__ float w_s[RES * 3];
    __shared__ int   base_s[RES];
    __shared__ int   cnt_s;
    __shared__ float S4[16], R4[16], Rinv[4], W4[16];
    __shared__ float T4[4 * 5], V4[4 * 5];
    __shared__ float rc2[2], rs2[2];
    __shared__ int   rp2[2], rq2[2];
    __shared__ float dvec[DIMX], mus[DIMX], gvec[4];

    const int b = blockIdx.x;
    const int t = threadIdx.x;
    const int sub = t / 96;      // 0..3
    const int tt  = t - sub * 96;

    // ---------------- Phase 0: sparse basis (warp 0) ----------------
    if (t == 0) cnt_s = 0;
    if (t < 32) {
        const int uj = t;
        const float u = (float)((double)uj / 31.0);
        {   // Nu (p=2): 3-wide window; identical guarded recurrence
            int s = -1;
            for (int i = 0; i < 70; i++)
                if (knU(i) <= u && u < knU(i + 1)) s = i;
            float w[4] = {0.0f, 0.0f, 0.0f, 0.0f};
            int base = 0;
            if (s >= 0) {
                base = s - 2;
                w[2] = 1.0f;
#pragma unroll
                for (int d = 1; d <= 2; d++) {
#pragma unroll
                    for (int a = 0; a < 3; a++) {
                        int i = s - 2 + a;
                        float ld = knU(i + d) - knU(i);
                        float rd = knU(i + d + 1) - knU(i + 1);
                        float t1 = (ld == 0.0f) ? 0.0f : (u - knU(i)) / ld * w[a];
                        float t2 = (rd == 0.0f) ? 0.0f : (knU(i + d + 1) - u) / rd * w[a + 1];
                        w[a] = t1 + t2;
                    }
                }
            }
            base_s[uj] = base;
            w_s[uj * 3 + 0] = w[0];
            w_s[uj * 3 + 1] = w[1];
            w_s[uj * 3 + 2] = w[2];
        }
        {   // Nv (q=3): only the sum
            int s = -1;
            for (int i = 0; i < 71; i++)
                if (knV(i) <= u && u < knV(i + 1)) s = i;
            float v[5] = {0.0f, 0.0f, 0.0f, 0.0f, 0.0f};
            if (s >= 0) {
                v[3] = 1.0f;
#pragma unroll
                for (int d = 1; d <= 3; d++) {
#pragma unroll
                    for (int a = 0; a < 4; a++) {
                        int i = s - 3 + a;
                        float ld = knV(i + d) - knV(i);
                        float rd = knV(i + d + 1) - knV(i + 1);
                        float t1 = (ld == 0.0f) ? 0.0f : (u - knV(i)) / ld * v[a];
                        float t2 = (rd == 0.0f) ? 0.0f : (knV(i + d + 1) - u) / rd * v[a + 1];
                        v[a] = t1 + t2;
                    }
                }
            }
            sv_s[uj] = v[0] + v[1] + v[2] + v[3];
        }
    }
    __syncthreads();

    // ---------------- Phase 1a: pipelined, 32 batches/block ----------------
    float colP_acc = 0.0f, colL_acc = 0.0f;
    const int u = tt / 3, c = tt - u * 3;
    const int base = base_s[u];
    const float w0 = w_s[u * 3], w1 = w_s[u * 3 + 1], w2 = w_s[u * 3 + 2];

    float rp[3], rl[3];
    {   // preload iteration 0
        int batch = b * 32 + sub;
#pragma unroll
        for (int k = 0; k < 3; k++) {
            int i = tt + k * 96;
            if (i < 204) {
                rp[k] = pred[batch * 204 + i];
                rl[k] = label[batch * 204 + i];
            }
        }
    }
    int pbuf = 0;
    for (int it = 0; it < 8; it++) {
        // store staged registers into smem buffer pbuf
        float* sp = &sPL[pbuf * 1632];
#pragma unroll
        for (int k = 0; k < 3; k++) {
            int i = tt + k * 96;
            if (i < 204) {
                sp[sub * 204 + i]       = rp[k];
                sp[816 + sub * 204 + i] = rl[k];
            }
        }
        __syncthreads();
        // prefetch next iteration (global loads overlap this iteration's math)
        if (it < 7) {
            int batch = b * 32 + (it + 1) * 4 + sub;
#pragma unroll
            for (int k = 0; k < 3; k++) {
                int i = tt + k * 96;
                if (i < 204) {
                    rp[k] = pred[batch * 204 + i];
                    rl[k] = label[batch * 204 + i];
                }
            }
        }
        // curves (3 FMA each)
        const float* cp = &sp[sub * 204];
        const float* cl = &sp[816 + sub * 204];
        float aP = cp[(base + 0) * 3 + c] * w0 + cp[(base + 1) * 3 + c] * w1 +
                   cp[(base + 2) * 3 + c] * w2;
        float aL = cl[(base + 0) * 3 + c] * w0 + cl[(base + 1) * 3 + c] * w1 +
                   cl[(base + 2) * 3 + c] * w2;
        Xsm[(it * 4 + sub) * 96 + tt]      = aP;
        Xsm[(32 + it * 4 + sub) * 96 + tt] = aL;
        float* cb = &cPL[pbuf * 768];
        cb[sub * 96 + tt]       = aP;
        cb[384 + sub * 96 + tt] = aL;
        colP_acc += aP;
        colL_acc += aL;
        __syncthreads();
        if (tt < 32) {   // IoU on this buffer (safe: buffer reused 2 iters later)
            float p0 = cb[sub * 96 + tt * 3], p1 = cb[sub * 96 + tt * 3 + 1], p2 = cb[sub * 96 + tt * 3 + 2];
            float l0 = cb[384 + sub * 96 + tt * 3], l1 = cb[384 + sub * 96 + tt * 3 + 1], l2 = cb[384 + sub * 96 + tt * 3 + 2];
            int cnt = 0;
#pragma unroll
            for (int v = 0; v < RES; v++) {
                float sv = sv_s[v];
                float d0 = p0 * sv - l0 * sv;
                float d1 = p1 * sv - l1 * sv;
                float d2 = p2 * sv - l2 * sv;
                float s = (d0 * d0 + d1 * d1) + d2 * d2;
                cnt += (s < 0.25f) ? 1 : 0;
            }
#pragma unroll
            for (int o = 16; o > 0; o >>= 1)
                cnt += __shfl_down_sync(0xffffffffu, cnt, o);
            if (tt == 0) atomicAdd(&cnt_s, cnt);
        }
        pbuf ^= 1;
    }
    __syncthreads();
    // colsum partials (4 subs -> 1) via buffer 0
    cPL[sub * 96 + tt]       = colP_acc;
    cPL[384 + sub * 96 + tt] = colL_acc;
    __syncthreads();
    if (sub == 0) {
        g_colP[b * 96 + tt] = cPL[tt] + cPL[96 + tt] + cPL[192 + tt] + cPL[288 + tt];
        g_colL[b * 96 + tt] = cPL[384 + tt] + cPL[480 + tt] + cPL[576 + tt] + cPL[672 + tt];
    }
    if (t == 0) g_cnt[b] = cnt_s;
    __syncthreads();

    // ---------------- Phase 1b: Gram of this block's own 64 rows --------------
    {
        const int ti = t / 24, tj = t - (t / 24) * 24;   // 16 x 24
        const int i0 = ti * 6, j0 = tj * 4;
        float acc[24];
#pragma unroll
        for (int k = 0; k < 24; k++) acc[k] = 0.0f;
#pragma unroll 4
        for (int row = 0; row < 64; row++) {
            const float* xr = &Xsm[row * 96];
            float2 A0 = *(const float2*)(xr + i0);
            float2 A1 = *(const float2*)(xr + i0 + 2);
            float2 A2 = *(const float2*)(xr + i0 + 4);
            float4 Bv = *(const float4*)(xr + j0);
            float xi[6] = {A0.x, A0.y, A1.x, A1.y, A2.x, A2.y};
            float xj[4] = {Bv.x, Bv.y, Bv.z, Bv.w};
#pragma unroll
            for (int a = 0; a < 6; a++)
#pragma unroll
                for (int bb = 0; bb < 4; bb++)
                    acc[a * 4 + bb] += xi[a] * xj[bb];
        }
#pragma unroll
        for (int a = 0; a < 6; a++)
#pragma unroll
            for (int bb = 0; bb < 4; bb++)
                atomicAdd(&g_S[(i0 + a) * 96 + (j0 + bb)], acc[a * 4 + bb]);
    }

    // ---------------- Barrier (arrive; block 0 waits) ----------------
    __syncthreads();
    if (t == 0) { __threadfence(); atomicAdd(&g_bar2, 1); }
    if (b != 0) return;
    if (t == 0) {
        while (atomicAdd(&g_bar2, 0) < NBLK) __nanosleep(100);
        __threadfence();
    }
    __syncthreads();

    // ---------------- Phase 2 (block 0 only): eig + finalize ----------------
    if (t < DIMX) {
        double sp = 0.0, sl = 0.0;
        for (int k = 0; k < NBLK; k++) {
            sp += (double)g_colP[k * 96 + t];
            sl += (double)g_colL[k * 96 + t];
        }
        mus[t]  = (float)((sp + sl) / 4096.0);
        dvec[t] = (float)(sp / 2048.0 - sl / 2048.0);
    }
    __syncthreads();
    for (int idx = t; idx < 96 * 96; idx += NTHR) {
        int i = idx / 96, j = idx - i * 96;
        float val = g_S[idx];
        C[i * 97 + j] = (val - 4096.0f * mus[i] * mus[j]) * (1.0f / 4095.0f);
        g_S[idx] = 0.0f;   // re-zero for next graph replay
    }
    if (t < 96) {
#pragma unroll
        for (int s = 0; s < 4; s++)
            Y0[t * 4 + s] = cosf(0.7f * (float)((t + 1) * (s + 1))) +
                            ((t == s) ? 0.05f : 0.0f);
    }
    __syncthreads();

    float* cur = Y0;
    float* prv = Y1;
    const int r = t % 96;
    const int g = t / 96;

    // cache this thread's 24 C entries in registers (invariant across matvecs)
    float creg[24];
#pragma unroll
    for (int jj = 0; jj < 24; jj++)
        creg[jj] = C[r * 97 + g * 24 + jj];

#define MATVEC(SRC)                                                       \
    {                                                                     \
        float a0=0,a1=0,a2=0,a3=0;                                        \
        int j0_ = g * 24;                                                 \
        _Pragma("unroll")                                                 \
        for (int jj = 0; jj < 24; jj++) {                                 \
            float cc_ = creg[jj];                                         \
            float4 y = *(const float4*)&SRC[(j0_ + jj) * 4];              \
            a0 += cc_ * y.x; a1 += cc_ * y.y; a2 += cc_ * y.z; a3 += cc_ * y.w; \
        }                                                                 \
        *(float4*)&P[(g * 96 + r) * 4] = make_float4(a0, a1, a2, a3);     \
    }                                                                     \
    __syncthreads();

#define REDUCE3(ca, cb, cc, CUR, PRV, DST)                                \
    {                                                                     \
        float cy = P[t] + P[384 + t] + P[768 + t] + P[1152 + t];          \
        DST[t] = (ca) * cy + (cb) * CUR[t] + (cc) * PRV[t];               \
    }                                                                     \
    __syncthreads();

#define REDUCE2(ca, cb, CUR, DST)                                         \
    {                                                                     \
        float cy = P[t] + P[384 + t] + P[768 + t] + P[1152 + t];          \
        DST[t] = (ca) * cy + (cb) * CUR[t];                               \
    }                                                                     \
    __syncthreads();

#define GRAM4(SRC)                                                        \
    if (t < 64) {                                                         \
        int pair = t >> 2, sb = t & 3;                                    \
        int a = pair >> 2, bb = pair & 3;                                 \
        float s = 0.0f;                                                   \
        for (int i = sb * 24; i < sb * 24 + 24; i++)                      \
            s += SRC[i * 4 + a] * SRC[i * 4 + bb];                        \
        s += __shfl_down_sync(0xffffffffu, s, 1);                         \
        s += __shfl_down_sync(0xffffffffu, s, 2);                         \
        if (sb == 0) S4[pair] = s;                                        \
    }                                                                     \
    __syncthreads();

#define CHOL4()                                                           \
    if (t == 0) {                                                         \
        float tr = S4[0] + S4[5] + S4[10] + S4[15];                       \
        float ridge = 1e-6f * tr;                                         \
        _Pragma("unroll")                                                 \
        for (int k = 0; k < 4; k++) S4[k * 4 + k] += ridge;               \
        _Pragma("unroll")                                                 \
        for (int k = 0; k < 4; k++) {                                     \
            float dk = sqrtf(fmaxf(S4[k * 4 + k], 1e-30f));               \
            float inv = 1.0f / dk;                                        \
            R4[k * 4 + k] = dk; Rinv[k] = inv;                            \
            for (int j = k + 1; j < 4; j++)                               \
                R4[k * 4 + j] = S4[k * 4 + j] * inv;                      \
            for (int i = k + 1; i < 4; i++)                               \
                for (int j = i; j < 4; j++)                               \
                    S4[i * 4 + j] -= R4[k * 4 + i] * R4[k * 4 + j];       \
        }                                                                 \
    }                                                                     \
    __syncthreads();

#define RSOLVE(SRC, DST)                                                  \
    if (t < 96) {                                                         \
        float z[4], y[4];                                                 \
        _Pragma("unroll")                                                 \
        for (int s = 0; s < 4; s++) z[s] = SRC[t * 4 + s];                \
        _Pragma("unroll")                                                 \
        for (int s = 0; s < 4; s++) {                                     \
            float v = z[s];                                               \
            for (int k = 0; k < s; k++) v -= y[k] * R4[k * 4 + s];        \
            y[s] = v * Rinv[s];                                           \
        }                                                                 \
        _Pragma("unroll")                                                 \
        for (int s = 0; s < 4; s++) DST[t * 4 + s] = y[s];                \
    }                                                                     \
    __syncthreads();

    const float c1 = 2.0f / CHEB_B;
    const float c4 = 4.0f / CHEB_B;

    for (int stage = 0; stage < CHEB_STAGES; stage++) {
        MATVEC(cur);
        REDUCE2(c1, -1.0f, cur, prv);
        { float* tmp = cur; cur = prv; prv = tmp; }
        for (int k = 0; k < CHEB_DEG - 1; k++) {
            MATVEC(cur);
            REDUCE3(c4, -2.0f, -1.0f, cur, prv, prv);
            { float* tmp = cur; cur = prv; prv = tmp; }
        }
        GRAM4(cur);
        CHOL4();
        RSOLVE(cur, cur);
    }

    MATVEC(cur);
    REDUCE2(1.0f, 0.0f, cur, prv);

    if (t < 64) {
        int pair = t >> 2, sb = t & 3;
        int a = pair >> 2, bb = pair & 3;
        float s = 0.0f;
        for (int i = sb * 24; i < sb * 24 + 24; i++)
            s += cur[i * 4 + a] * prv[i * 4 + bb];
        s += __shfl_down_sync(0xffffffffu, s, 1);
        s += __shfl_down_sync(0xffffffffu, s, 2);
        if (sb == 0) W4[pair] = s;
    }
    __syncthreads();
    if (t < 16) {
        int a = t >> 2, bb = t & 3;
        T4[a * 5 + bb] = 0.5f * (W4[a * 4 + bb] + W4[bb * 4 + a]);
    }
    if (t >= 16 && t < 32) {
        int e = t - 16;
        int j = e >> 2, k = e & 3;
        V4[j * 5 + k] = (j == k) ? 1.0f : 0.0f;
    }
    __syncthreads();

    if (t >= 32 && t < 36) {
        int a = t - 32;
        float s = 0.0f;
        for (int i = 0; i < 96; i++) s += cur[i * 4 + a] * dvec[i];
        gvec[a] = s;
    }

    if (t < 32) {
        for (int sweep = 0; sweep < 6; sweep++) {
            for (int rr = 0; rr < 3; rr++) {
                if (t < 2) {
                    int p, q;
                    if (t == 0) { p = 3; q = rr; }
                    else { p = (rr + 1) % 3; q = (rr + 2) % 3; }
                    rp2[t] = p; rq2[t] = q;
                    float app = T4[p * 5 + p];
                    float aqq = T4[q * 5 + q];
                    float apq = T4[p * 5 + q];
                    float cc_ = 1.0f, ss_ = 0.0f;
                    if (fabsf(apq) > 1e-30f) {
                        float tau = (aqq - app) / (2.0f * apq);
                        float tv = (tau >= 0.0f)
                                       ? 1.0f / (tau + sqrtf(1.0f + tau * tau))
                                       : 1.0f / (tau - sqrtf(1.0f + tau * tau));
                        cc_ = rsqrtf(1.0f + tv * tv);
                        ss_ = tv * cc_;
                    }
                    rc2[t] = cc_; rs2[t] = ss_;
                }
                __syncwarp();
                if (t < 4) {
                    int a = t >> 1, bb = t & 1;
                    int pa = rp2[a], qa = rq2[a];
                    int pb = rp2[bb], qb = rq2[bb];
                    float ca = rc2[a], sa = rs2[a];
                    float cb2 = rc2[bb], sb2 = rs2[bb];
                    float x00 = T4[pa * 5 + pb], x01 = T4[pa * 5 + qb];
                    float x10 = T4[qa * 5 + pb], x11 = T4[qa * 5 + qb];
                    float y00 = ca * x00 - sa * x10;
                    float y01 = ca * x01 - sa * x11;
                    float y10 = sa * x00 + ca * x10;
                    float y11 = sa * x01 + ca * x11;
                    T4[pa * 5 + pb] = cb2 * y00 - sb2 * y01;
                    T4[pa * 5 + qb] = sb2 * y00 + cb2 * y01;
                    T4[qa * 5 + pb] = cb2 * y10 - sb2 * y11;
                    T4[qa * 5 + qb] = sb2 * y10 + cb2 * y11;
                }
                if (t >= 8 && t < 16) {
                    int e = t - 8;
                    int j = e >> 1, k = e & 1;
                    int p = rp2[k], q = rq2[k];
                    float cc_ = rc2[k], ss_ = rs2[k];
                    float vp = V4[j * 5 + p], vq = V4[j * 5 + q];
                    V4[j * 5 + p] = cc_ * vp - ss_ * vq;
                    V4[j * 5 + q] = ss_ * vp + cc_ * vq;
                }
                __syncwarp();
            }
        }
    }
    __syncthreads();

    if (t == 0) {
        int imin = 0;
        float vmin = T4[0];
#pragma unroll
        for (int i = 1; i < 4; i++) {
            float e = T4[i * 5 + i];
            if (e < vmin) { vmin = e; imin = i; }
        }
        float ssum = 0.0f;
#pragma unroll
        for (int k = 0; k < 4; k++) {
            if (k == imin) continue;
            float pr = 0.0f;
            for (int a = 0; a < 4; a++) pr += V4[a * 5 + k] * gvec[a];
            ssum += pr * pr;
        }
        float sv2 = 0.0f;
        for (int v = 0; v < RES; v++) sv2 += sv_s[v] * sv_s[v];
        float dist_pca = sqrtf(sv2) * sqrtf(ssum);
        float pca_loss = 1.0f - dist_pca;

        int icnt = 0;
        for (int k = 0; k < NBLK; k++) icnt += g_cnt[k];
        float inter = (float)icnt;
        float uni = 2048.0f - inter;   // reference: P + P - inter
        float iou_loss = 1.0f - inter / uni;

        out[0] = pca_loss + iou_loss;

        atomicExch(&g_bar2, 0);   // reset for next graph replay
    }
}

// -------------------- launcher --------------------
extern "C" void kernel_launch(void* const* d_in, const int* in_sizes, int n_in,
                              void* d_out, int out_size) {
    const float* pred  = (const float*)d_in[0];
    const float* label = (const float*)d_in[1];
    float* out = (float*)d_out;

    cudaFuncSetAttribute(k_fused, cudaFuncAttributeMaxDynamicSharedMemorySize,
                         DSM_BYTES);
    k_fused<<<NBLK, NTHR, DSM_BYTES>>>(pred, label, out);
}